// round 8
// baseline (speedup 1.0000x reference)
#include <cuda_runtime.h>
#include <cstdint>

#define NN 20000
#define EE 320000
#define DD 128
#define KK 8
#define HH 64
#define KH 512   // K*H

// ---------------- scratch (static device arrays) ----------------------------
__device__ float g_er[(size_t)NN * KK];            // node_feat @ W_r^T
__device__ float g_W2[KK * DD];                    // [k][d] reduced weights
__device__ float g_S[(size_t)NN * KK * DD];        // aggregated, normalized
__device__ int   g_cnt[NN];
__device__ int   g_off[NN + 1];
__device__ int   g_cur[NN];
__device__ int   g_list[EE];

// ---------------- prep: zero counts + W2 + er in one launch ------------------
// blocks [0,79): zero g_cnt ; [79,83): W2 ; [83,2583): er
__global__ __launch_bounds__(256) void prep_kernel(
    const float* __restrict__ nf, const float* __restrict__ Wr,
    const float* __restrict__ W_enc, const float* __restrict__ attn_l) {
    int b = blockIdx.x;
    int t = threadIdx.x;
    if (b < 79) {
        int i = b * 256 + t;
        if (i < NN) g_cnt[i] = 0;
    } else if (b < 83) {
        int idx = (b - 79) * 256 + t;
        if (idx < KK * DD) {
            int d = idx >> 3, k = idx & 7;
            float s = 0.0f;
#pragma unroll 8
            for (int h = 0; h < HH; h++)
                s += W_enc[(size_t)d * KH + k * HH + h] * attn_l[k * HH + h];
            g_W2[k * DD + d] = s;
        }
    } else {
        int warp = (b - 83) * 8 + (t >> 5);
        int lane = t & 31;
        if (warp >= NN) return;
        float4 x = *(const float4*)(nf + (size_t)warp * DD + lane * 4);
#pragma unroll
        for (int k = 0; k < KK; k++) {
            float4 w = *(const float4*)(Wr + (size_t)k * DD + lane * 4);
            float p = x.x * w.x + x.y * w.y + x.z * w.z + x.w * w.w;
#pragma unroll
            for (int off = 16; off > 0; off >>= 1)
                p += __shfl_xor_sync(0xffffffffu, p, off);
            if (lane == 0) g_er[(size_t)warp * KK + k] = p;
        }
    }
}

// ---------------- CSR build --------------------------------------------------
__global__ void hist_kernel(const int* __restrict__ dst) {
    int e = blockIdx.x * blockDim.x + threadIdx.x;
    if (e < EE) atomicAdd(&g_cnt[dst[e]], 1);
}

__global__ void scan_kernel() {   // single block, 1024 threads, 20 counts each
    __shared__ int part[1024];
    int t = threadIdx.x;
    int base = t * 20;
    int loc[20];
    int s = 0;
#pragma unroll
    for (int i = 0; i < 20; i++) {
        int idx = base + i;
        int c = (idx < NN) ? g_cnt[idx] : 0;
        loc[i] = s;
        s += c;
    }
    part[t] = s;
    __syncthreads();
    for (int off = 1; off < 1024; off <<= 1) {
        int v = (t >= off) ? part[t - off] : 0;
        __syncthreads();
        part[t] += v;
        __syncthreads();
    }
    int excl = (t == 0) ? 0 : part[t - 1];
#pragma unroll
    for (int i = 0; i < 20; i++) {
        int idx = base + i;
        if (idx < NN) {
            g_off[idx] = excl + loc[i];
            g_cur[idx] = excl + loc[i];
        }
    }
    if (t == 1023) g_off[NN] = part[1023];
}

__global__ void fill_kernel(const int* __restrict__ dst) {
    int e = blockIdx.x * blockDim.x + threadIdx.x;
    if (e < EE) {
        int p = atomicAdd(&g_cur[dst[e]], 1);
        g_list[p] = e;
    }
}

// ---------------- fused per-node: mean + logits + softmax + aggregate --------
// block = node; 8 warps, warp handles every 8th edge of the node.
// Per edge: mean over L=3 (regs), el_k = m . W2_k (butterfly), exp, accumulate.
__global__ __launch_bounds__(256) void fused_agg_kernel(
    const float* __restrict__ ef) {
    __shared__ float w2s[KK * DD];                 // 4 KB
    __shared__ float sm_acc[8][KK][DD / 4][4];     // 32 KB  [warp][k][d4][4]
    __shared__ float sm_ex[8][KK];                 // 256 B

    int n = blockIdx.x;
    int t = threadIdx.x;
    int w = t >> 5, lane = t & 31;

    for (int i = t; i < KK * DD; i += 256) w2s[i] = g_W2[i];

    // er[n][*] broadcast to all threads
    float4 er0 = *(const float4*)(g_er + (size_t)n * KK);
    float4 er1 = *(const float4*)(g_er + (size_t)n * KK + 4);
    float erv[8] = {er0.x, er0.y, er0.z, er0.w, er1.x, er1.y, er1.z, er1.w};

    int beg = g_off[n], end = g_off[n + 1];
    __syncthreads();   // w2s ready

    float acc[KK][4];
#pragma unroll
    for (int k = 0; k < KK; k++)
#pragma unroll
        for (int j = 0; j < 4; j++) acc[k][j] = 0.0f;
    float exsum[KK];
#pragma unroll
    for (int k = 0; k < KK; k++) exsum[k] = 0.0f;

    for (int c = beg + w; c < end; c += 8) {
        int e = g_list[c];                          // broadcast load
        size_t base = (size_t)e * 3 * DD + lane * 4;
        float4 a = *(const float4*)(ef + base);
        float4 b = *(const float4*)(ef + base + DD);
        float4 c3 = *(const float4*)(ef + base + 2 * DD);
        const float s = 1.0f / 3.0f;
        float4 m;
        m.x = (a.x + b.x + c3.x) * s;
        m.y = (a.y + b.y + c3.y) * s;
        m.z = (a.z + b.z + c3.z) * s;
        m.w = (a.w + b.w + c3.w) * s;

        float pk[KK];
#pragma unroll
        for (int k = 0; k < KK; k++) {
            float4 wv = *(const float4*)(w2s + k * DD + lane * 4);
            pk[k] = m.x * wv.x + m.y * wv.y + m.z * wv.z + m.w * wv.w;
        }
#pragma unroll
        for (int off = 16; off > 0; off >>= 1)
#pragma unroll
            for (int k = 0; k < KK; k++)
                pk[k] += __shfl_xor_sync(0xffffffffu, pk[k], off);

#pragma unroll
        for (int k = 0; k < KK; k++) {
            float v = pk[k] + erv[k];
            v = (v > 0.0f) ? v : 0.01f * v;
            float exv = expf(v);
            exsum[k] += exv;
            acc[k][0] += exv * m.x;
            acc[k][1] += exv * m.y;
            acc[k][2] += exv * m.z;
            acc[k][3] += exv * m.w;
        }
    }

    // stage per-warp partials
#pragma unroll
    for (int k = 0; k < KK; k++) {
        *(float4*)&sm_acc[w][k][lane][0] =
            make_float4(acc[k][0], acc[k][1], acc[k][2], acc[k][3]);
        if (lane == 0) sm_ex[w][k] = exsum[k];
    }
    __syncthreads();

    // reduce over warps: thread (k = t>>5, d4 = lane)
    int k = w;             // reuse: warp index == head for reduction
    float4 sum = make_float4(0.f, 0.f, 0.f, 0.f);
    float es = 0.0f;
#pragma unroll
    for (int ww = 0; ww < 8; ww++) {
        float4 v = *(const float4*)&sm_acc[ww][k][lane][0];
        sum.x += v.x; sum.y += v.y; sum.z += v.z; sum.w += v.w;
        es += sm_ex[ww][k];
    }
    float scale = (es > 0.0f) ? (1.0f / es) : 0.0f;
    sum.x *= scale; sum.y *= scale; sum.z *= scale; sum.w *= scale;
    *(float4*)(g_S + ((size_t)n * KK + k) * DD + lane * 4) = sum;
}

// ---------------- final small GEMM: out[n,k,:] = S[n,k,:] @ W_enc[:,kH:kH+H] -
#define CP 132   // S smem stride (16B-aligned rows, 4-bank shift)
#define WP 65    // W smem stride
#define SMEM_C ((64 * CP + DD * WP) * 4)
__global__ __launch_bounds__(256) void out_gemm_kernel(
    const float* __restrict__ W_enc, float* __restrict__ out) {
    extern __shared__ float smc[];
    float* Ss = smc;              // [64][CP]
    float* Ws = smc + 64 * CP;    // [DD][WP]

    int t = threadIdx.x;
    int n0 = blockIdx.x * 64;
    int k = blockIdx.y;

#pragma unroll
    for (int i = 0; i < 32; i++) {
        int idx = i * 256 + t;         // 8192
        int d = idx >> 6, h = idx & 63;
        Ws[d * WP + h] = W_enc[(size_t)d * KH + k * HH + h];
    }
#pragma unroll
    for (int i = 0; i < 8; i++) {
        int idx = i * 256 + t;         // 2048 float4s
        int r = idx >> 5, c4 = idx & 31;
        int n = n0 + r;
        float4 v = (n < NN)
            ? *(const float4*)(g_S + ((size_t)n * KK + k) * DD + c4 * 4)
            : make_float4(0.f, 0.f, 0.f, 0.f);
        *(float4*)(Ss + r * CP + c4 * 4) = v;
    }
    __syncthreads();

    int tx = t & 15, ty = t >> 4;
    float c[4][4];
#pragma unroll
    for (int i = 0; i < 4; i++)
#pragma unroll
        for (int j = 0; j < 4; j++) c[i][j] = 0.0f;

#pragma unroll 8
    for (int d = 0; d < DD; d++) {
        float av[4], bv[4];
#pragma unroll
        for (int i = 0; i < 4; i++) av[i] = Ss[(ty * 4 + i) * CP + d];
#pragma unroll
        for (int j = 0; j < 4; j++) bv[j] = Ws[d * WP + tx * 4 + j];
#pragma unroll
        for (int i = 0; i < 4; i++)
#pragma unroll
            for (int j = 0; j < 4; j++) c[i][j] += av[i] * bv[j];
    }

#pragma unroll
    for (int i = 0; i < 4; i++) {
        int n = n0 + ty * 4 + i;
        if (n < NN) {
            *(float4*)(out + (size_t)n * KH + k * HH + tx * 4) =
                make_float4(c[i][0], c[i][1], c[i][2], c[i][3]);
        }
    }
}

// ---------------- launch -----------------------------------------------------
extern "C" void kernel_launch(void* const* d_in, const int* in_sizes, int n_in,
                              void* d_out, int out_size) {
    const float* node_feat = (const float*)d_in[0];   // (N,128)
    const float* edge_feat = (const float*)d_in[1];   // (E,3,128)
    const float* W_enc     = (const float*)d_in[2];   // (128,512)
    const float* attn_l    = (const float*)d_in[3];   // (1,8,64)
    const float* W_r       = (const float*)d_in[4];   // (8,128)
    const int*   dst       = (const int*)d_in[5];     // (E,)
    float* out = (float*)d_out;                       // (N,8,64)

    cudaFuncSetAttribute(out_gemm_kernel,
                         cudaFuncAttributeMaxDynamicSharedMemorySize, SMEM_C);

    prep_kernel<<<2583, 256>>>(node_feat, W_r, W_enc, attn_l);
    hist_kernel<<<EE / 256, 256>>>(dst);
    scan_kernel<<<1, 1024>>>();
    fill_kernel<<<EE / 256, 256>>>(dst);
    fused_agg_kernel<<<NN, 256>>>(edge_feat);
    out_gemm_kernel<<<dim3((NN + 63) / 64, KK), 256, SMEM_C>>>(W_enc, out);
}

// round 9
// speedup vs baseline: 1.2349x; 1.2349x over previous
#include <cuda_runtime.h>
#include <cstdint>

#define NN 20000
#define EE 320000
#define DD 128
#define KK 8
#define HH 64
#define KH 512   // K*H

// ---------------- scratch (static device arrays, zero-initialized) ----------
__device__ float g_mean[(size_t)EE * DD];          // mean features (e-order)
__device__ float g_ex[(size_t)EE * KK];            // exp(logits)
__device__ float g_er[(size_t)NN * KK];            // node_feat @ W_r^T
__device__ float g_W2[KK * DD];                    // [k][d] reduced weights
__device__ float g_S[(size_t)NN * KK * DD];        // aggregated, normalized
__device__ int   g_cnt[NN];                        // zero at entry (see scan)
__device__ int   g_off[NN + 1];
__device__ int   g_cur[NN];
__device__ int   g_list[EE];

// ---------------- prep: W2 + er ----------------------------------------------
// blocks [0,4): W2 ; [4,2504): er
__global__ __launch_bounds__(256) void prep_kernel(
    const float* __restrict__ nf, const float* __restrict__ Wr,
    const float* __restrict__ W_enc, const float* __restrict__ attn_l) {
    int b = blockIdx.x;
    int t = threadIdx.x;
    if (b < 4) {
        int idx = b * 256 + t;
        if (idx < KK * DD) {
            int d = idx >> 3, k = idx & 7;
            float s = 0.0f;
#pragma unroll 8
            for (int h = 0; h < HH; h++)
                s += W_enc[(size_t)d * KH + k * HH + h] * attn_l[k * HH + h];
            g_W2[k * DD + d] = s;
        }
    } else {
        int warp = (b - 4) * 8 + (t >> 5);
        int lane = t & 31;
        if (warp >= NN) return;
        float4 x = *(const float4*)(nf + (size_t)warp * DD + lane * 4);
#pragma unroll
        for (int k = 0; k < KK; k++) {
            float4 w = *(const float4*)(Wr + (size_t)k * DD + lane * 4);
            float p = x.x * w.x + x.y * w.y + x.z * w.z + x.w * w.w;
#pragma unroll
            for (int off = 16; off > 0; off >>= 1)
                p += __shfl_xor_sync(0xffffffffu, p, off);
            if (lane == 0) g_er[(size_t)warp * KK + k] = p;
        }
    }
}

// ---------------- CSR build --------------------------------------------------
__global__ void hist_kernel(const int* __restrict__ dst) {
    int e = blockIdx.x * blockDim.x + threadIdx.x;
    if (e < EE) atomicAdd(&g_cnt[dst[e]], 1);
}

__global__ void scan_kernel() {   // single block, 1024 threads, 20 counts each
    __shared__ int part[1024];
    int t = threadIdx.x;
    int base = t * 20;
    int loc[20];
    int s = 0;
#pragma unroll
    for (int i = 0; i < 20; i++) {
        int idx = base + i;
        int c = (idx < NN) ? g_cnt[idx] : 0;
        loc[i] = s;
        s += c;
    }
    part[t] = s;
    __syncthreads();
    for (int off = 1; off < 1024; off <<= 1) {
        int v = (t >= off) ? part[t - off] : 0;
        __syncthreads();
        part[t] += v;
        __syncthreads();
    }
    int excl = (t == 0) ? 0 : part[t - 1];
#pragma unroll
    for (int i = 0; i < 20; i++) {
        int idx = base + i;
        if (idx < NN) {
            g_off[idx] = excl + loc[i];
            g_cur[idx] = excl + loc[i];
            g_cnt[idx] = 0;            // leave zeroed for next launch call
        }
    }
    if (t == 1023) g_off[NN] = part[1023];
}

__global__ void fill_kernel(const int* __restrict__ dst) {
    int e = blockIdx.x * blockDim.x + threadIdx.x;
    if (e < EE) {
        int p = atomicAdd(&g_cur[dst[e]], 1);
        g_list[p] = e;
    }
}

// ---------------- mean + logits + exp (one warp per edge, fold reduction) ----
__global__ __launch_bounds__(256) void mean_logits_kernel(
    const float* __restrict__ ef, const int* __restrict__ dst) {
    __shared__ float w2s[KK * DD];
    int t = threadIdx.x;
    for (int i = t; i < KK * DD; i += 256) w2s[i] = g_W2[i];
    __syncthreads();

    int warp = blockIdx.x * 8 + (t >> 5);   // EE/8 blocks, always full
    int lane = t & 31;

    size_t base = (size_t)warp * 3 * DD + lane * 4;
    float4 a = *(const float4*)(ef + base);
    float4 b = *(const float4*)(ef + base + DD);
    float4 c = *(const float4*)(ef + base + 2 * DD);
    const float s = 1.0f / 3.0f;
    float4 m;
    m.x = (a.x + b.x + c.x) * s;
    m.y = (a.y + b.y + c.y) * s;
    m.z = (a.z + b.z + c.z) * s;
    m.w = (a.w + b.w + c.w) * s;
    *(float4*)(g_mean + (size_t)warp * DD + lane * 4) = m;

    float pk[KK];
#pragma unroll
    for (int k = 0; k < KK; k++) {
        float4 w = *(const float4*)(w2s + k * DD + lane * 4);
        pk[k] = m.x * w.x + m.y * w.y + m.z * w.z + m.w * w.w;
    }
    // fold reduction: 8 values -> 1 value/lane in 9 SHFLs
    // fold off=16: keep heads (lane&16? i+4 : i)
    float v4[4];
#pragma unroll
    for (int i = 0; i < 4; i++) {
        float send = (lane & 16) ? pk[i] : pk[i + 4];
        float recv = __shfl_xor_sync(0xffffffffu, send, 16);
        v4[i] = ((lane & 16) ? pk[i + 4] : pk[i]) + recv;
    }
    // fold off=8
    float v2[2];
#pragma unroll
    for (int i = 0; i < 2; i++) {
        float send = (lane & 8) ? v4[i] : v4[i + 2];
        float recv = __shfl_xor_sync(0xffffffffu, send, 8);
        v2[i] = ((lane & 8) ? v4[i + 2] : v4[i]) + recv;
    }
    // fold off=4
    {
        float send = (lane & 4) ? v2[0] : v2[1];
        float recv = __shfl_xor_sync(0xffffffffu, send, 4);
        v2[0] = ((lane & 4) ? v2[1] : v2[0]) + recv;
    }
    // reduce remaining lane bits 0,1
    v2[0] += __shfl_xor_sync(0xffffffffu, v2[0], 1);
    v2[0] += __shfl_xor_sync(0xffffffffu, v2[0], 2);
    // lane holds el for head k = (lane>>2)&7

    int d = dst[warp];
    if ((lane & 3) == 0) {
        int k = lane >> 2;
        float v = v2[0] + g_er[(size_t)d * KK + k];
        v = (v > 0.0f) ? v : 0.01f * v;
        g_ex[(size_t)warp * KK + k] = expf(v);
    }
}

// ---------------- per-node gather-aggregate (staged via smem) ----------------
// block = node; thread t: k = t>>5, d4 = t&31 owns S[n][k][d4*4..+3]
#define BATCH 32
__global__ __launch_bounds__(256) void aggregate_kernel() {
    __shared__ float ms[BATCH][DD];      // 16 KB
    __shared__ float exs[BATCH][KK];     // 1 KB
    int n = blockIdx.x;
    int t = threadIdx.x;
    int k = t >> 5, d4 = t & 31;
    int beg = g_off[n], end = g_off[n + 1];

    float4 acc = make_float4(0.f, 0.f, 0.f, 0.f);
    float exsum = 0.0f;

    for (int p0 = beg; p0 < end; p0 += BATCH) {
        int nb = end - p0;
        if (nb > BATCH) nb = BATCH;
        // stage nb edge rows (each 512B contiguous) into smem
        for (int i = t; i < nb * 32; i += 256) {
            int j = i >> 5, c4 = i & 31;
            int e = g_list[p0 + j];
            *(float4*)&ms[j][c4 * 4] =
                *(const float4*)(g_mean + (size_t)e * DD + c4 * 4);
        }
        if (t < nb * KK) {
            int j = t >> 3, kk = t & 7;
            int e = g_list[p0 + j];
            exs[j][kk] = g_ex[(size_t)e * KK + kk];
        }
        __syncthreads();
#pragma unroll 4
        for (int j = 0; j < nb; j++) {
            float ev = exs[j][k];
            float4 mv = *(const float4*)&ms[j][d4 * 4];
            acc.x += ev * mv.x; acc.y += ev * mv.y;
            acc.z += ev * mv.z; acc.w += ev * mv.w;
            exsum += ev;
        }
        __syncthreads();
    }
    float scale = (exsum > 0.0f) ? (1.0f / exsum) : 0.0f;
    acc.x *= scale; acc.y *= scale; acc.z *= scale; acc.w *= scale;
    *(float4*)(g_S + ((size_t)n * KK + k) * DD + d4 * 4) = acc;
}

// ---------------- final small GEMM: out[n,k,:] = S[n,k,:] @ W_enc[:,kH:kH+H] -
#define CP 132   // S smem stride (16B-aligned rows, 4-bank shift)
#define WP 65    // W smem stride
#define SMEM_C ((64 * CP + DD * WP) * 4)
__global__ __launch_bounds__(256) void out_gemm_kernel(
    const float* __restrict__ W_enc, float* __restrict__ out) {
    extern __shared__ float smc[];
    float* Ss = smc;              // [64][CP]
    float* Ws = smc + 64 * CP;    // [DD][WP]

    int t = threadIdx.x;
    int n0 = blockIdx.x * 64;
    int k = blockIdx.y;

#pragma unroll
    for (int i = 0; i < 32; i++) {
        int idx = i * 256 + t;         // 8192
        int d = idx >> 6, h = idx & 63;
        Ws[d * WP + h] = W_enc[(size_t)d * KH + k * HH + h];
    }
#pragma unroll
    for (int i = 0; i < 8; i++) {
        int idx = i * 256 + t;         // 2048 float4s
        int r = idx >> 5, c4 = idx & 31;
        int n = n0 + r;
        float4 v = (n < NN)
            ? *(const float4*)(g_S + ((size_t)n * KK + k) * DD + c4 * 4)
            : make_float4(0.f, 0.f, 0.f, 0.f);
        *(float4*)(Ss + r * CP + c4 * 4) = v;
    }
    __syncthreads();

    int tx = t & 15, ty = t >> 4;
    float c[4][4];
#pragma unroll
    for (int i = 0; i < 4; i++)
#pragma unroll
        for (int j = 0; j < 4; j++) c[i][j] = 0.0f;

#pragma unroll 8
    for (int d = 0; d < DD; d++) {
        float av[4], bv[4];
#pragma unroll
        for (int i = 0; i < 4; i++) av[i] = Ss[(ty * 4 + i) * CP + d];
#pragma unroll
        for (int j = 0; j < 4; j++) bv[j] = Ws[d * WP + tx * 4 + j];
#pragma unroll
        for (int i = 0; i < 4; i++)
#pragma unroll
            for (int j = 0; j < 4; j++) c[i][j] += av[i] * bv[j];
    }

#pragma unroll
    for (int i = 0; i < 4; i++) {
        int n = n0 + ty * 4 + i;
        if (n < NN) {
            *(float4*)(out + (size_t)n * KH + k * HH + tx * 4) =
                make_float4(c[i][0], c[i][1], c[i][2], c[i][3]);
        }
    }
}

// ---------------- launch -----------------------------------------------------
extern "C" void kernel_launch(void* const* d_in, const int* in_sizes, int n_in,
                              void* d_out, int out_size) {
    const float* node_feat = (const float*)d_in[0];   // (N,128)
    const float* edge_feat = (const float*)d_in[1];   // (E,3,128)
    const float* W_enc     = (const float*)d_in[2];   // (128,512)
    const float* attn_l    = (const float*)d_in[3];   // (1,8,64)
    const float* W_r       = (const float*)d_in[4];   // (8,128)
    const int*   dst       = (const int*)d_in[5];     // (E,)
    float* out = (float*)d_out;                       // (N,8,64)

    cudaFuncSetAttribute(out_gemm_kernel,
                         cudaFuncAttributeMaxDynamicSharedMemorySize, SMEM_C);

    prep_kernel<<<2504, 256>>>(node_feat, W_r, W_enc, attn_l);
    hist_kernel<<<EE / 256, 256>>>(dst);
    scan_kernel<<<1, 1024>>>();
    fill_kernel<<<EE / 256, 256>>>(dst);
    mean_logits_kernel<<<EE / 8, 256>>>(edge_feat, dst);
    aggregate_kernel<<<NN, 256>>>();
    out_gemm_kernel<<<dim3((NN + 63) / 64, KK), 256, SMEM_C>>>(W_enc, out);
}

// round 11
// speedup vs baseline: 1.3178x; 1.0672x over previous
#include <cuda_runtime.h>
#include <cuda_fp16.h>
#include <cstdint>

#define NN 20000
#define EE 320000
#define DD 128
#define KK 8
#define HH 64
#define KH 512   // K*H

// ---------------- scratch (static device arrays, zero-initialized) ----------
__device__ __half g_meanh[(size_t)EE * DD];        // 82 MB mean features (fp16)
__device__ float g_ex[(size_t)EE * KK];            // exp(logits)
__device__ float g_er[(size_t)NN * KK];            // node_feat @ W_r^T
__device__ float g_W2[KK * DD];                    // [k][d] reduced weights
__device__ float g_S[(size_t)NN * KK * DD];        // aggregated, normalized
__device__ int   g_cnt[NN];                        // zero at entry (scan re-zeroes)
__device__ int   g_off[NN + 1];
__device__ int   g_cur[NN];
__device__ int   g_list[EE];

// ---------------- K1: W2 + er + histogram (all independent) ------------------
// blocks [0,4): W2 ; [4,2504): er ; blocks [0,1250) also histogram 256 edges
__global__ __launch_bounds__(256) void prep_hist_kernel(
    const float* __restrict__ nf, const float* __restrict__ Wr,
    const float* __restrict__ W_enc, const float* __restrict__ attn_l,
    const int* __restrict__ dst) {
    int b = blockIdx.x;
    int t = threadIdx.x;
    if (b < 1250) {                       // histogram part
        int e = b * 256 + t;
        atomicAdd(&g_cnt[dst[e]], 1);
    }
    if (b < 4) {
        int idx = b * 256 + t;
        if (idx < KK * DD) {
            int d = idx >> 3, k = idx & 7;
            float s = 0.0f;
#pragma unroll 8
            for (int h = 0; h < HH; h++)
                s += W_enc[(size_t)d * KH + k * HH + h] * attn_l[k * HH + h];
            g_W2[k * DD + d] = s;
        }
    } else {
        int warp = (b - 4) * 8 + (t >> 5);
        int lane = t & 31;
        if (warp >= NN) return;
        float4 x = *(const float4*)(nf + (size_t)warp * DD + lane * 4);
#pragma unroll
        for (int k = 0; k < KK; k++) {
            float4 w = *(const float4*)(Wr + (size_t)k * DD + lane * 4);
            float p = x.x * w.x + x.y * w.y + x.z * w.z + x.w * w.w;
#pragma unroll
            for (int off = 16; off > 0; off >>= 1)
                p += __shfl_xor_sync(0xffffffffu, p, off);
            if (lane == 0) g_er[(size_t)warp * KK + k] = p;
        }
    }
}

// ---------------- K2: scan (single block) ------------------------------------
__global__ void scan_kernel() {   // 1024 threads, 20 counts each
    __shared__ int part[1024];
    int t = threadIdx.x;
    int base = t * 20;
    int loc[20];
    int s = 0;
#pragma unroll
    for (int i = 0; i < 20; i++) {
        int idx = base + i;
        int c = (idx < NN) ? g_cnt[idx] : 0;
        loc[i] = s;
        s += c;
    }
    part[t] = s;
    __syncthreads();
    for (int off = 1; off < 1024; off <<= 1) {
        int v = (t >= off) ? part[t - off] : 0;
        __syncthreads();
        part[t] += v;
        __syncthreads();
    }
    int excl = (t == 0) ? 0 : part[t - 1];
#pragma unroll
    for (int i = 0; i < 20; i++) {
        int idx = base + i;
        if (idx < NN) {
            g_off[idx] = excl + loc[i];
            g_cur[idx] = excl + loc[i];
            g_cnt[idx] = 0;            // leave zeroed for next launch call
        }
    }
    if (t == 1023) g_off[NN] = part[1023];
}

// ---------------- K3: mean + logits + exp, plus CSR fill ---------------------
// one warp per edge; blocks [0,1250) additionally fill g_list for 256 edges
__global__ __launch_bounds__(256) void mean_logits_fill_kernel(
    const float* __restrict__ ef, const int* __restrict__ dst) {
    __shared__ float w2s[KK * DD];
    int t = threadIdx.x;

    if (blockIdx.x < 1250) {              // fill part (needs scan done: K2)
        int e = blockIdx.x * 256 + t;
        int p = atomicAdd(&g_cur[dst[e]], 1);
        g_list[p] = e;
    }

    for (int i = t; i < KK * DD; i += 256) w2s[i] = g_W2[i];
    __syncthreads();

    int warp = blockIdx.x * 8 + (t >> 5);   // EE/8 blocks, always full
    int lane = t & 31;

    size_t base = (size_t)warp * 3 * DD + lane * 4;
    float4 a = *(const float4*)(ef + base);
    float4 b = *(const float4*)(ef + base + DD);
    float4 c = *(const float4*)(ef + base + 2 * DD);
    const float s = 1.0f / 3.0f;
    float4 m;
    m.x = (a.x + b.x + c.x) * s;
    m.y = (a.y + b.y + c.y) * s;
    m.z = (a.z + b.z + c.z) * s;
    m.w = (a.w + b.w + c.w) * s;

    // fp16 store (logits below use exact fp32 m)
    __half2 h0 = __floats2half2_rn(m.x, m.y);
    __half2 h1 = __floats2half2_rn(m.z, m.w);
    uint2 u;
    u.x = *reinterpret_cast<uint32_t*>(&h0);
    u.y = *reinterpret_cast<uint32_t*>(&h1);
    *(uint2*)(g_meanh + (size_t)warp * DD + lane * 4) = u;

    float pk[KK];
#pragma unroll
    for (int k = 0; k < KK; k++) {
        float4 w = *(const float4*)(w2s + k * DD + lane * 4);
        pk[k] = m.x * w.x + m.y * w.y + m.z * w.z + m.w * w.w;
    }
    // fold reduction: 8 values -> 1 value/lane in 9 SHFLs
    float v4[4];
#pragma unroll
    for (int i = 0; i < 4; i++) {
        float send = (lane & 16) ? pk[i] : pk[i + 4];
        float recv = __shfl_xor_sync(0xffffffffu, send, 16);
        v4[i] = ((lane & 16) ? pk[i + 4] : pk[i]) + recv;
    }
    float v2[2];
#pragma unroll
    for (int i = 0; i < 2; i++) {
        float send = (lane & 8) ? v4[i] : v4[i + 2];
        float recv = __shfl_xor_sync(0xffffffffu, send, 8);
        v2[i] = ((lane & 8) ? v4[i + 2] : v4[i]) + recv;
    }
    {
        float send = (lane & 4) ? v2[0] : v2[1];
        float recv = __shfl_xor_sync(0xffffffffu, send, 4);
        v2[0] = ((lane & 4) ? v2[1] : v2[0]) + recv;
    }
    v2[0] += __shfl_xor_sync(0xffffffffu, v2[0], 1);
    v2[0] += __shfl_xor_sync(0xffffffffu, v2[0], 2);
    // lane holds el for head k = lane>>2 (lanes where lane&3==0)

    int d = dst[warp];
    if ((lane & 3) == 0) {
        int k = lane >> 2;
        float v = v2[0] + g_er[(size_t)d * KK + k];
        v = (v > 0.0f) ? v : 0.01f * v;
        g_ex[(size_t)warp * KK + k] = expf(v);
    }
}

// ---------------- K4: per-node gather-aggregate (staged fp16 rows) -----------
// block = node; thread t: k = t>>5, d4 = t&31 owns S[n][k][d4*4..+3]
#define BATCH 32
__global__ __launch_bounds__(256) void aggregate_kernel() {
    __shared__ __half msh[BATCH][DD];    // 8 KB
    __shared__ float exs[BATCH][KK];     // 1 KB
    int n = blockIdx.x;
    int t = threadIdx.x;
    int k = t >> 5, d4 = t & 31;
    int beg = g_off[n], end = g_off[n + 1];

    float4 acc = make_float4(0.f, 0.f, 0.f, 0.f);
    float exsum = 0.0f;

    for (int p0 = beg; p0 < end; p0 += BATCH) {
        int nb = end - p0;
        if (nb > BATCH) nb = BATCH;
        // stage nb rows (256B each, contiguous) as fp16
        for (int i = t; i < nb * 16; i += 256) {
            int j = i >> 4, c8 = i & 15;
            int e = g_list[p0 + j];
            *(uint4*)&msh[j][c8 * 8] =
                *(const uint4*)(g_meanh + (size_t)e * DD + c8 * 8);
        }
        if (t < nb * KK) {
            int j = t >> 3, kk = t & 7;
            int e = g_list[p0 + j];
            exs[j][kk] = g_ex[(size_t)e * KK + kk];
        }
        __syncthreads();
#pragma unroll 4
        for (int j = 0; j < nb; j++) {
            float ev = exs[j][k];
            uint2 r = *(const uint2*)&msh[j][d4 * 4];
            __half2 h0 = *reinterpret_cast<__half2*>(&r.x);
            __half2 h1 = *reinterpret_cast<__half2*>(&r.y);
            float2 f0 = __half22float2(h0);
            float2 f1 = __half22float2(h1);
            acc.x += ev * f0.x; acc.y += ev * f0.y;
            acc.z += ev * f1.x; acc.w += ev * f1.y;
            exsum += ev;
        }
        __syncthreads();
    }
    float scale = (exsum > 0.0f) ? (1.0f / exsum) : 0.0f;
    acc.x *= scale; acc.y *= scale; acc.z *= scale; acc.w *= scale;
    *(float4*)(g_S + ((size_t)n * KK + k) * DD + d4 * 4) = acc;
}

// ---------------- K5: out[n,k,:] = S[n,k,:] @ W_enc[:,kH:kH+H] ---------------
#define CP 132   // S smem stride (16B-aligned rows, 4-bank shift)
#define WP 65    // W smem stride
#define SMEM_C ((64 * CP + DD * WP) * 4)
__global__ __launch_bounds__(256) void out_gemm_kernel(
    const float* __restrict__ W_enc, float* __restrict__ out) {
    extern __shared__ float smc[];
    float* Ss = smc;              // [64][CP]
    float* Ws = smc + 64 * CP;    // [DD][WP]

    int t = threadIdx.x;
    int n0 = blockIdx.x * 64;
    int k = blockIdx.y;

#pragma unroll
    for (int i = 0; i < 32; i++) {
        int idx = i * 256 + t;         // 8192
        int d = idx >> 6, h = idx & 63;
        Ws[d * WP + h] = W_enc[(size_t)d * KH + k * HH + h];
    }
#pragma unroll
    for (int i = 0; i < 8; i++) {
        int idx = i * 256 + t;         // 2048 float4s
        int r = idx >> 5, c4 = idx & 31;
        int n = n0 + r;
        float4 v = (n < NN)
            ? *(const float4*)(g_S + ((size_t)n * KK + k) * DD + c4 * 4)
            : make_float4(0.f, 0.f, 0.f, 0.f);
        *(float4*)(Ss + r * CP + c4 * 4) = v;
    }
    __syncthreads();

    int tx = t & 15, ty = t >> 4;
    float c[4][4];
#pragma unroll
    for (int i = 0; i < 4; i++)
#pragma unroll
        for (int j = 0; j < 4; j++) c[i][j] = 0.0f;

#pragma unroll 8
    for (int d = 0; d < DD; d++) {
        float av[4], bv[4];
#pragma unroll
        for (int i = 0; i < 4; i++) av[i] = Ss[(ty * 4 + i) * CP + d];
#pragma unroll
        for (int j = 0; j < 4; j++) bv[j] = Ws[d * WP + tx * 4 + j];
#pragma unroll
        for (int i = 0; i < 4; i++)
#pragma unroll
            for (int j = 0; j < 4; j++) c[i][j] += av[i] * bv[j];
    }

#pragma unroll
    for (int i = 0; i < 4; i++) {
        int n = n0 + ty * 4 + i;
        if (n < NN) {
            *(float4*)(out + (size_t)n * KH + k * HH + tx * 4) =
                make_float4(c[i][0], c[i][1], c[i][2], c[i][3]);
        }
    }
}

// ---------------- launch -----------------------------------------------------
extern "C" void kernel_launch(void* const* d_in, const int* in_sizes, int n_in,
                              void* d_out, int out_size) {
    const float* node_feat = (const float*)d_in[0];   // (N,128)
    const float* edge_feat = (const float*)d_in[1];   // (E,3,128)
    const float* W_enc     = (const float*)d_in[2];   // (128,512)
    const float* attn_l    = (const float*)d_in[3];   // (1,8,64)
    const float* W_r       = (const float*)d_in[4];   // (8,128)
    const int*   dst       = (const int*)d_in[5];     // (E,)
    float* out = (float*)d_out;                       // (N,8,64)

    cudaFuncSetAttribute(out_gemm_kernel,
                         cudaFuncAttributeMaxDynamicSharedMemorySize, SMEM_C);

    prep_hist_kernel<<<2504, 256>>>(node_feat, W_r, W_enc, attn_l, dst);
    scan_kernel<<<1, 1024>>>();
    mean_logits_fill_kernel<<<EE / 8, 256>>>(edge_feat, dst);
    aggregate_kernel<<<NN, 256>>>();
    out_gemm_kernel<<<dim3((NN + 63) / 64, KK), 256, SMEM_C>>>(W_enc, out);
}